// round 3
// baseline (speedup 1.0000x reference)
#include <cuda_runtime.h>

#define DIMX 200
#define DIMY 200
#define DIMZ 16
#define NDIMS 16
#define KWIN 6
#define VOXEL 0.4f
#define VMINX -40.0f
#define VMINY -40.0f
#define VMINZ -1.0f

// Tiles: 4 x 4 x 16 voxels = 256 voxels = 256 threads/block
#define TX 4
#define TY 4
#define NTX (DIMX / TX)          // 50
#define NTY (DIMY / TY)          // 50
#define NTILES (NTX * NTY)       // 2500
#define CAP 256                  // ids per bin (expected ~40, Poisson-safe)
#define CHUNK 64                 // gaussians staged in smem per iteration
#define NMAX 65536

// Scratch (static device globals, zero-initialized at load; gather resets
// counters after use so every launch sees zeros — no separate memset kernel)
__device__ int   g_cnt[NTILES];
__device__ int   g_ids[NTILES * CAP];
__device__ float g_prec[NMAX * 12];  // mx,my,mz,i00 | i01,i02,i11,i12 | i22,op,startP,endP

// ---------------------------------------------------------------------------
// Kernel 1: per-gaussian precompute (icov, bbox) + scatter id into tile bins
// ---------------------------------------------------------------------------
__global__ void k_bin(const float* __restrict__ means,
                      const float* __restrict__ covs,
                      const float* __restrict__ opac,
                      int n) {
    int g = blockIdx.x * blockDim.x + threadIdx.x;
    if (g >= n) return;

    const float* c = covs + g * 9;
    float a00 = c[0], a01 = c[1], a02 = c[2];
    float a11 = c[4], a12 = c[5], a22 = c[8];
    float c00 = a11 * a22 - a12 * a12;
    float c01 = a02 * a12 - a01 * a22;
    float c02 = a01 * a12 - a02 * a11;
    float det = a00 * c00 + a01 * c01 + a02 * c02;
    float inv = 1.0f / det;
    float i00 = c00 * inv;
    float i01 = c01 * inv;
    float i02 = c02 * inv;
    float i11 = (a00 * a22 - a02 * a02) * inv;
    float i12 = (a01 * a02 - a00 * a12) * inv;
    float i22 = (a00 * a11 - a01 * a01) * inv;

    float mx = means[g * 3 + 0];
    float my = means[g * 3 + 1];
    float mz = means[g * 3 + 2];
    float rx = 3.0f * sqrtf(a00);
    float ry = 3.0f * sqrtf(a11);
    float rz = 3.0f * sqrtf(a22);

    // trunc-toward-zero matches reference (coords positive after shift)
    int sx = max(0, (int)((mx - rx - VMINX) / VOXEL));
    int sy = max(0, (int)((my - ry - VMINY) / VOXEL));
    int sz = max(0, (int)((mz - rz - VMINZ) / VOXEL));
    int ex = min(DIMX, (int)((mx + rx - VMINX) / VOXEL) + 1);
    int ey = min(DIMY, (int)((my + ry - VMINY) / VOXEL) + 1);
    int ez = min(DIMZ, (int)((mz + rz - VMINZ) / VOXEL) + 1);
    // reference only visits offs in [0, K)
    ex = min(ex, sx + KWIN);
    ey = min(ey, sy + KWIN);
    ez = min(ez, sz + KWIN);

    int sP = sx | (sy << 8) | (sz << 16);
    int eP = ex | (ey << 8) | (ez << 16);

    float4* p = (float4*)(g_prec + (size_t)g * 12);
    p[0] = make_float4(mx, my, mz, i00);
    p[1] = make_float4(i01, i02, i11, i12);
    p[2] = make_float4(i22, opac[g], __int_as_float(sP), __int_as_float(eP));

    if (sx >= ex || sy >= ey || sz >= ez) return;

    int tx0 = sx / TX, tx1 = (ex - 1) / TX;
    int ty0 = sy / TY, ty1 = (ey - 1) / TY;
    for (int tx = tx0; tx <= tx1; tx++)
        for (int ty = ty0; ty <= ty1; ty++) {
            int t = tx * NTY + ty;
            int slot = atomicAdd(&g_cnt[t], 1);
            if (slot < CAP) g_ids[t * CAP + slot] = g;
        }
}

// ---------------------------------------------------------------------------
// Kernel 2: gather. One block per 4x4x16 tile, one thread per voxel.
// Warp layout: ix fixed per warp -> x-cull is a warp-uniform branch.
// Accumulates density + 16 feature channels in registers, normalizes inline,
// writes final output. No atomics, no init pass, no separate normalize pass.
// ---------------------------------------------------------------------------
__global__ __launch_bounds__(256) void k_gather(const float4* __restrict__ feat4,
                                                float* __restrict__ gdens,
                                                float* __restrict__ gfeat) {
    __shared__ float4 s_prec[CHUNK * 3];
    __shared__ float4 s_feat[CHUNK * 4];
    __shared__ int    s_ids[CHUNK];

    const int b = blockIdx.x;
    const int ty = b % NTY;
    const int tx = b / NTY;
    const int t = threadIdx.x;

    const int lz = t & 15;
    const int ly = (t >> 4) & 3;
    const int lx = t >> 6;            // warp-uniform (warp = 2 y-rows x 16 z)
    const int ix = tx * TX + lx;
    const int iy = ty * TY + ly;
    const int iz = lz;

    const float px = (float)ix * VOXEL + VMINX;
    const float py = (float)iy * VOXEL + VMINY;
    const float pz = (float)iz * VOXEL + VMINZ;

    const int n = min(g_cnt[b], CAP);
    const int* __restrict__ bin = g_ids + b * CAP;

    float accd = 0.0f;
    float f0x = 0, f0y = 0, f0z = 0, f0w = 0;
    float f1x = 0, f1y = 0, f1z = 0, f1w = 0;
    float f2x = 0, f2y = 0, f2z = 0, f2w = 0;
    float f3x = 0, f3y = 0, f3z = 0, f3w = 0;

    const float4* prec4 = (const float4*)g_prec;

    for (int base = 0; base < n; base += CHUNK) {
        const int m = min(CHUNK, n - base);

        if (t < m) s_ids[t] = bin[base + t];
        __syncthreads();

        for (int i = t; i < m * 3; i += 256) {
            int j = i / 3;
            s_prec[i] = prec4[(size_t)s_ids[j] * 3 + (i - j * 3)];
        }
        for (int i = t; i < m * 4; i += 256) {
            s_feat[i] = feat4[(size_t)s_ids[i >> 2] * 4 + (i & 3)];
        }
        __syncthreads();

        for (int j = 0; j < m; j++) {
            float4 p2 = s_prec[j * 3 + 2];
            int sP = __float_as_int(p2.z);
            int eP = __float_as_int(p2.w);
            // warp-uniform x cull
            if (ix < (sP & 255) || ix >= (eP & 255)) continue;
            bool pass = (iy >= ((sP >> 8) & 255)) & (iy < ((eP >> 8) & 255))
                      & (iz >= (sP >> 16)) & (iz < (eP >> 16));
            if (pass) {
                float4 p0 = s_prec[j * 3 + 0];
                float4 p1 = s_prec[j * 3 + 1];
                float dx = px - p0.x;
                float dy = py - p0.y;
                float dz = pz - p0.z;
                float mahal = p0.w * dx * dx + p1.z * dy * dy + p2.x * dz * dz
                            + 2.0f * (p1.x * dx * dy + p1.y * dx * dz + p1.w * dy * dz);
                float dens = p2.y * __expf(-0.5f * mahal);
                accd += dens;
                float4 q0 = s_feat[j * 4 + 0];
                float4 q1 = s_feat[j * 4 + 1];
                float4 q2 = s_feat[j * 4 + 2];
                float4 q3 = s_feat[j * 4 + 3];
                f0x += dens * q0.x; f0y += dens * q0.y; f0z += dens * q0.z; f0w += dens * q0.w;
                f1x += dens * q1.x; f1y += dens * q1.y; f1z += dens * q1.z; f1w += dens * q1.w;
                f2x += dens * q2.x; f2y += dens * q2.y; f2z += dens * q2.z; f2w += dens * q2.w;
                f3x += dens * q3.x; f3y += dens * q3.y; f3z += dens * q3.z; f3w += dens * q3.w;
            }
        }
        __syncthreads();
    }

    // reset bin counter for the next launch (keeps the no-memset invariant)
    if (t == 0) g_cnt[b] = 0;

    const int idx = (ix * DIMY + iy) * DIMZ + iz;
    gdens[idx] = accd;

    const float s = 1.0f / fmaxf(accd, 1e-6f);
    f3w += 1e-5f;  // reference seeds channel 15 with 1e-5 before normalize
    float4* fp = (float4*)(gfeat + (size_t)idx * NDIMS);
    fp[0] = make_float4(f0x * s, f0y * s, f0z * s, f0w * s);
    fp[1] = make_float4(f1x * s, f1y * s, f1z * s, f1w * s);
    fp[2] = make_float4(f2x * s, f2y * s, f2z * s, f2w * s);
    fp[3] = make_float4(f3x * s, f3y * s, f3z * s, f3w * s);
}

extern "C" void kernel_launch(void* const* d_in, const int* in_sizes, int n_in,
                              void* d_out, int out_size) {
    const float* means = (const float*)d_in[0];   // [N,3]
    const float* covs  = (const float*)d_in[1];   // [N,3,3]
    const float* opac  = (const float*)d_in[2];   // [N]
    const float* feats = (const float*)d_in[3];   // [N,16]
    const int n_gauss = in_sizes[2];

    float* gdens = (float*)d_out;                                  // [200*200*16]
    float* gfeat = gdens + (size_t)DIMX * DIMY * DIMZ;             // [...,16]

    k_bin<<<(n_gauss + 127) / 128, 128>>>(means, covs, opac, n_gauss);
    k_gather<<<NTILES, 256>>>((const float4*)feats, gdens, gfeat);
}

// round 7
// speedup vs baseline: 1.0074x; 1.0074x over previous
#include <cuda_runtime.h>

#define DIMX 200
#define DIMY 200
#define DIMZ 16
#define NDIMS 16
#define KWIN 6
#define VOXEL 0.4f
#define VMINX -40.0f
#define VMINY -40.0f
#define VMINZ -1.0f

// Tiles: 4 x 4 x 16 voxels = 256 voxels = 256 threads/block
#define TX 4
#define TY 4
#define NTX (DIMX / TX)          // 50
#define NTY (DIMY / TY)          // 50
#define NTILES (NTX * NTY)       // 2500
#define CAP 256                  // ids per bin (expected ~34, Poisson-safe)
#define CHUNK 64                 // gaussians staged in smem per iteration
#define NMAX 65536

// Scratch (static device globals, zero-initialized at load; gather resets
// counters after use so every launch sees zeros — no separate memset kernel)
__device__ int   g_cnt[NTILES];
__device__ int   g_ids[NTILES * CAP];
__device__ float g_prec[NMAX * 12];  // mx,my,mz,i00 | i01,i02,i11,i12 | i22,op,startP,endP

// ---------------------------------------------------------------------------
// Kernel 1: per-gaussian precompute (icov, bbox) + scatter id into tile bins
// ---------------------------------------------------------------------------
__global__ void k_bin(const float* __restrict__ means,
                      const float* __restrict__ covs,
                      const float* __restrict__ opac,
                      int n) {
    int g = blockIdx.x * blockDim.x + threadIdx.x;
    if (g >= n) return;

    const float* c = covs + g * 9;
    float a00 = c[0], a01 = c[1], a02 = c[2];
    float a11 = c[4], a12 = c[5], a22 = c[8];
    float c00 = a11 * a22 - a12 * a12;
    float c01 = a02 * a12 - a01 * a22;
    float c02 = a01 * a12 - a02 * a11;
    float det = a00 * c00 + a01 * c01 + a02 * c02;
    float inv = 1.0f / det;
    float i00 = c00 * inv;
    float i01 = c01 * inv;
    float i02 = c02 * inv;
    float i11 = (a00 * a22 - a02 * a02) * inv;
    float i12 = (a01 * a02 - a00 * a12) * inv;
    float i22 = (a00 * a11 - a01 * a01) * inv;

    float mx = means[g * 3 + 0];
    float my = means[g * 3 + 1];
    float mz = means[g * 3 + 2];
    float rx = 3.0f * sqrtf(a00);
    float ry = 3.0f * sqrtf(a11);
    float rz = 3.0f * sqrtf(a22);

    // trunc-toward-zero matches reference (coords positive after shift)
    int sx = max(0, (int)((mx - rx - VMINX) / VOXEL));
    int sy = max(0, (int)((my - ry - VMINY) / VOXEL));
    int sz = max(0, (int)((mz - rz - VMINZ) / VOXEL));
    int ex = min(DIMX, (int)((mx + rx - VMINX) / VOXEL) + 1);
    int ey = min(DIMY, (int)((my + ry - VMINY) / VOXEL) + 1);
    int ez = min(DIMZ, (int)((mz + rz - VMINZ) / VOXEL) + 1);
    // reference only visits offs in [0, K)
    ex = min(ex, sx + KWIN);
    ey = min(ey, sy + KWIN);
    ez = min(ez, sz + KWIN);

    int sP = sx | (sy << 8) | (sz << 16);
    int eP = ex | (ey << 8) | (ez << 16);

    float4* p = (float4*)(g_prec + (size_t)g * 12);
    p[0] = make_float4(mx, my, mz, i00);
    p[1] = make_float4(i01, i02, i11, i12);
    p[2] = make_float4(i22, opac[g], __int_as_float(sP), __int_as_float(eP));

    if (sx >= ex || sy >= ey || sz >= ez) return;

    int tx0 = sx / TX, tx1 = (ex - 1) / TX;
    int ty0 = sy / TY, ty1 = (ey - 1) / TY;
    for (int tx = tx0; tx <= tx1; tx++)
        for (int ty = ty0; ty <= ty1; ty++) {
            int t = tx * NTY + ty;
            int slot = atomicAdd(&g_cnt[t], 1);
            if (slot < CAP) g_ids[t * CAP + slot] = g;
        }
}

// ---------------------------------------------------------------------------
// Kernel 2: gather. One block per 4x4x16 tile, one thread per voxel.
// Warp layout: lane = lx | (ly<<2) | (dz<<4); warp w owns z in {2w, 2w+1}.
// -> z (the smallest gaussian extent) is culled warp-uniformly: only ~2 of 8
// warps execute the eval body per gaussian; xy predicated per lane.
// Accumulates density + 16 feature channels in registers, normalizes inline,
// writes final output. No atomics, no init pass, no separate normalize pass.
// ---------------------------------------------------------------------------
__global__ __launch_bounds__(256) void k_gather(const float4* __restrict__ feat4,
                                                float* __restrict__ gdens,
                                                float* __restrict__ gfeat) {
    __shared__ float4 s_prec[CHUNK * 3];
    __shared__ float4 s_feat[CHUNK * 4];
    __shared__ int    s_ids[CHUNK];

    const int b = blockIdx.x;
    const int ty = b % NTY;
    const int tx = b / NTY;
    const int t = threadIdx.x;

    const int lane = t & 31;
    const int w = t >> 5;             // warp id = z slab
    const int lx = lane & 3;
    const int ly = (lane >> 2) & 3;
    const int iz = 2 * w + (lane >> 4);
    const int zb = 2 * w;             // warp-uniform z base
    const int ix = tx * TX + lx;
    const int iy = ty * TY + ly;

    const float px = (float)ix * VOXEL + VMINX;
    const float py = (float)iy * VOXEL + VMINY;
    const float pz = (float)iz * VOXEL + VMINZ;

    const int n = min(g_cnt[b], CAP);
    const int* __restrict__ bin = g_ids + b * CAP;

    float accd = 0.0f;
    float f0x = 0, f0y = 0, f0z = 0, f0w = 0;
    float f1x = 0, f1y = 0, f1z = 0, f1w = 0;
    float f2x = 0, f2y = 0, f2z = 0, f2w = 0;
    float f3x = 0, f3y = 0, f3z = 0, f3w = 0;

    const float4* prec4 = (const float4*)g_prec;

    for (int base = 0; base < n; base += CHUNK) {
        const int m = min(CHUNK, n - base);

        if (t < m) s_ids[t] = bin[base + t];
        __syncthreads();

        for (int i = t; i < m * 3; i += 256) {
            int j = i / 3;
            s_prec[i] = prec4[(size_t)s_ids[j] * 3 + (i - j * 3)];
        }
        for (int i = t; i < m * 4; i += 256) {
            s_feat[i] = feat4[(size_t)s_ids[i >> 2] * 4 + (i & 3)];
        }
        __syncthreads();

        for (int j = 0; j < m; j++) {
            float4 p2 = s_prec[j * 3 + 2];
            int sP = __float_as_int(p2.z);
            int eP = __float_as_int(p2.w);
            int zlo = sP >> 16;
            int zhi = eP >> 16;
            // warp-uniform z cull: warp owns z in [zb, zb+2)
            if (zhi <= zb || zlo >= zb + 2) continue;
            bool pass = (ix >= (sP & 255)) & (ix < (eP & 255))
                      & (iy >= ((sP >> 8) & 255)) & (iy < ((eP >> 8) & 255))
                      & (iz >= zlo) & (iz < zhi);
            if (pass) {
                float4 p0 = s_prec[j * 3 + 0];
                float4 p1 = s_prec[j * 3 + 1];
                float dx = px - p0.x;
                float dy = py - p0.y;
                float dz = pz - p0.z;
                float mahal = p0.w * dx * dx + p1.z * dy * dy + p2.x * dz * dz
                            + 2.0f * (p1.x * dx * dy + p1.y * dx * dz + p1.w * dy * dz);
                float dens = p2.y * __expf(-0.5f * mahal);
                accd += dens;
                float4 q0 = s_feat[j * 4 + 0];
                float4 q1 = s_feat[j * 4 + 1];
                float4 q2 = s_feat[j * 4 + 2];
                float4 q3 = s_feat[j * 4 + 3];
                f0x += dens * q0.x; f0y += dens * q0.y; f0z += dens * q0.z; f0w += dens * q0.w;
                f1x += dens * q1.x; f1y += dens * q1.y; f1z += dens * q1.z; f1w += dens * q1.w;
                f2x += dens * q2.x; f2y += dens * q2.y; f2z += dens * q2.z; f2w += dens * q2.w;
                f3x += dens * q3.x; f3y += dens * q3.y; f3z += dens * q3.z; f3w += dens * q3.w;
            }
        }
        __syncthreads();
    }

    // reset bin counter for the next launch (keeps the no-memset invariant)
    if (t == 0) g_cnt[b] = 0;

    const int idx = (ix * DIMY + iy) * DIMZ + iz;
    gdens[idx] = accd;

    const float s = 1.0f / fmaxf(accd, 1e-6f);
    f3w += 1e-5f;  // reference seeds channel 15 with 1e-5 before normalize
    float4* fp = (float4*)(gfeat + (size_t)idx * NDIMS);
    fp[0] = make_float4(f0x * s, f0y * s, f0z * s, f0w * s);
    fp[1] = make_float4(f1x * s, f1y * s, f1z * s, f1w * s);
    fp[2] = make_float4(f2x * s, f2y * s, f2z * s, f2w * s);
    fp[3] = make_float4(f3x * s, f3y * s, f3z * s, f3w * s);
}

extern "C" void kernel_launch(void* const* d_in, const int* in_sizes, int n_in,
                              void* d_out, int out_size) {
    const float* means = (const float*)d_in[0];   // [N,3]
    const float* covs  = (const float*)d_in[1];   // [N,3,3]
    const float* opac  = (const float*)d_in[2];   // [N]
    const float* feats = (const float*)d_in[3];   // [N,16]
    const int n_gauss = in_sizes[2];

    float* gdens = (float*)d_out;                                  // [200*200*16]
    float* gfeat = gdens + (size_t)DIMX * DIMY * DIMZ;             // [...,16]

    k_bin<<<(n_gauss + 255) / 256, 256>>>(means, covs, opac, n_gauss);
    k_gather<<<NTILES, 256>>>((const float4*)feats, gdens, gfeat);
}

// round 9
// speedup vs baseline: 1.1066x; 1.0985x over previous
#include <cuda_runtime.h>

#define DIMX 200
#define DIMY 200
#define DIMZ 16
#define NDIMS 16
#define KWIN 6
#define VOXEL 0.4f
#define VMINX -40.0f
#define VMINY -40.0f
#define VMINZ -1.0f

// Tiles: 4 x 4 x 16 voxels = 256 voxels = 256 threads/block
#define TX 4
#define TY 4
#define NTX (DIMX / TX)          // 50
#define NTY (DIMY / TY)          // 50
#define NTILES (NTX * NTY)       // 2500
#define CAP 256                  // ids per bin (expected ~34, Poisson-safe)
#define CHUNK 64                 // gaussians staged in smem per iteration
#define NMAX 65536

// Scratch (static device globals, zero-initialized at load; gather resets
// counters after use so every launch sees zeros — no separate memset kernel)
__device__ int   g_cnt[NTILES];
__device__ int   g_ids[NTILES * CAP];
__device__ float g_prec[NMAX * 12];  // mx,my,mz,i00 | i01,i02,i11,i12 | i22,op,startP,endP

// ---------------------------------------------------------------------------
// Kernel 1: per-gaussian precompute (icov, bbox) + scatter id into tile bins
// ---------------------------------------------------------------------------
__global__ void k_bin(const float* __restrict__ means,
                      const float* __restrict__ covs,
                      const float* __restrict__ opac,
                      int n) {
    int g = blockIdx.x * blockDim.x + threadIdx.x;
    if (g >= n) return;

    const float* c = covs + g * 9;
    float a00 = c[0], a01 = c[1], a02 = c[2];
    float a11 = c[4], a12 = c[5], a22 = c[8];
    float c00 = a11 * a22 - a12 * a12;
    float c01 = a02 * a12 - a01 * a22;
    float c02 = a01 * a12 - a02 * a11;
    float det = a00 * c00 + a01 * c01 + a02 * c02;
    float inv = 1.0f / det;
    float i00 = c00 * inv;
    float i01 = c01 * inv;
    float i02 = c02 * inv;
    float i11 = (a00 * a22 - a02 * a02) * inv;
    float i12 = (a01 * a02 - a00 * a12) * inv;
    float i22 = (a00 * a11 - a01 * a01) * inv;

    float mx = means[g * 3 + 0];
    float my = means[g * 3 + 1];
    float mz = means[g * 3 + 2];
    float rx = 3.0f * sqrtf(a00);
    float ry = 3.0f * sqrtf(a11);
    float rz = 3.0f * sqrtf(a22);

    // trunc-toward-zero matches reference (coords positive after shift)
    int sx = max(0, (int)((mx - rx - VMINX) / VOXEL));
    int sy = max(0, (int)((my - ry - VMINY) / VOXEL));
    int sz = max(0, (int)((mz - rz - VMINZ) / VOXEL));
    int ex = min(DIMX, (int)((mx + rx - VMINX) / VOXEL) + 1);
    int ey = min(DIMY, (int)((my + ry - VMINY) / VOXEL) + 1);
    int ez = min(DIMZ, (int)((mz + rz - VMINZ) / VOXEL) + 1);
    // reference only visits offs in [0, K)
    ex = min(ex, sx + KWIN);
    ey = min(ey, sy + KWIN);
    ez = min(ez, sz + KWIN);

    int sP = sx | (sy << 8) | (sz << 16);
    int eP = ex | (ey << 8) | (ez << 16);

    float4* p = (float4*)(g_prec + (size_t)g * 12);
    p[0] = make_float4(mx, my, mz, i00);
    p[1] = make_float4(i01, i02, i11, i12);
    p[2] = make_float4(i22, opac[g], __int_as_float(sP), __int_as_float(eP));

    if (sx >= ex || sy >= ey || sz >= ez) return;

    int tx0 = sx / TX, tx1 = (ex - 1) / TX;
    int ty0 = sy / TY, ty1 = (ey - 1) / TY;
    for (int tx = tx0; tx <= tx1; tx++)
        for (int ty = ty0; ty <= ty1; ty++) {
            int t = tx * NTY + ty;
            int slot = atomicAdd(&g_cnt[t], 1);
            if (slot < CAP) g_ids[t * CAP + slot] = g;
        }
}

// ---------------------------------------------------------------------------
// Kernel 2: gather. One block per 4x4x16 tile, one thread per voxel.
// Warp layout: lane = lx | (ly<<2) | (dz<<4); warp w owns z in {2w, 2w+1}.
// Per chunk: lanes cull gaussians in parallel against the warp's z-slab,
// ballot-compact survivors into a per-warp worklist, then evaluate densely.
// Accumulates density + 16 feature channels in registers, normalizes inline,
// writes final output. No atomics on output, no init/normalize passes.
// ---------------------------------------------------------------------------
__global__ __launch_bounds__(256) void k_gather(const float4* __restrict__ feat4,
                                                float* __restrict__ gdens,
                                                float* __restrict__ gfeat) {
    __shared__ float4 s_prec[CHUNK * 3];
    __shared__ float4 s_feat[CHUNK * 4];
    __shared__ int    s_ids[CHUNK];
    __shared__ short  s_wl[8][CHUNK];   // per-warp compacted survivor indices

    const int b = blockIdx.x;
    const int ty = b % NTY;
    const int tx = b / NTY;
    const int t = threadIdx.x;

    const int lane = t & 31;
    const int w = t >> 5;             // warp id = z slab
    const int lx = lane & 3;
    const int ly = (lane >> 2) & 3;
    const int iz = 2 * w + (lane >> 4);
    const int zb = 2 * w;             // warp-uniform z base
    const int ix = tx * TX + lx;
    const int iy = ty * TY + ly;

    const float px = (float)ix * VOXEL + VMINX;
    const float py = (float)iy * VOXEL + VMINY;
    const float pz = (float)iz * VOXEL + VMINZ;

    const int n = min(g_cnt[b], CAP);
    const int* __restrict__ bin = g_ids + b * CAP;

    float accd = 0.0f;
    float f0x = 0, f0y = 0, f0z = 0, f0w = 0;
    float f1x = 0, f1y = 0, f1z = 0, f1w = 0;
    float f2x = 0, f2y = 0, f2z = 0, f2w = 0;
    float f3x = 0, f3y = 0, f3z = 0, f3w = 0;

    const float4* prec4 = (const float4*)g_prec;

    for (int base = 0; base < n; base += CHUNK) {
        const int m = min(CHUNK, n - base);

        if (t < m) s_ids[t] = bin[base + t];
        __syncthreads();

        for (int i = t; i < m * 3; i += 256) {
            int j = i / 3;
            s_prec[i] = prec4[(size_t)s_ids[j] * 3 + (i - j * 3)];
        }
        for (int i = t; i < m * 4; i += 256) {
            s_feat[i] = feat4[(size_t)s_ids[i >> 2] * 4 + (i & 3)];
        }
        __syncthreads();

        // ---- lane-parallel z-cull + ballot compaction into s_wl[w] ----
        int mc = 0;
        for (int i0 = 0; i0 < m; i0 += 32) {
            int i = i0 + lane;
            bool zpass = false;
            if (i < m) {
                float4 p2 = s_prec[i * 3 + 2];
                int zlo = __float_as_int(p2.z) >> 16;
                int zhi = __float_as_int(p2.w) >> 16;
                zpass = (zhi > zb) && (zlo < zb + 2);
            }
            unsigned bal = __ballot_sync(0xFFFFFFFFu, zpass);
            if (zpass) {
                int pos = mc + __popc(bal & ((1u << lane) - 1u));
                s_wl[w][pos] = (short)i;
            }
            mc += __popc(bal);
        }
        __syncwarp();

        // ---- dense eval over survivors ----
        for (int k = 0; k < mc; k++) {
            int j = s_wl[w][k];
            float4 p2 = s_prec[j * 3 + 2];
            int sP = __float_as_int(p2.z);
            int eP = __float_as_int(p2.w);
            bool pass = (ix >= (sP & 255)) & (ix < (eP & 255))
                      & (iy >= ((sP >> 8) & 255)) & (iy < ((eP >> 8) & 255))
                      & (iz >= (sP >> 16)) & (iz < (eP >> 16));
            if (pass) {
                float4 p0 = s_prec[j * 3 + 0];
                float4 p1 = s_prec[j * 3 + 1];
                float dx = px - p0.x;
                float dy = py - p0.y;
                float dz = pz - p0.z;
                float mahal = p0.w * dx * dx + p1.z * dy * dy + p2.x * dz * dz
                            + 2.0f * (p1.x * dx * dy + p1.y * dx * dz + p1.w * dy * dz);
                float dens = p2.y * __expf(-0.5f * mahal);
                accd += dens;
                float4 q0 = s_feat[j * 4 + 0];
                float4 q1 = s_feat[j * 4 + 1];
                float4 q2 = s_feat[j * 4 + 2];
                float4 q3 = s_feat[j * 4 + 3];
                f0x += dens * q0.x; f0y += dens * q0.y; f0z += dens * q0.z; f0w += dens * q0.w;
                f1x += dens * q1.x; f1y += dens * q1.y; f1z += dens * q1.z; f1w += dens * q1.w;
                f2x += dens * q2.x; f2y += dens * q2.y; f2z += dens * q2.z; f2w += dens * q2.w;
                f3x += dens * q3.x; f3y += dens * q3.y; f3z += dens * q3.z; f3w += dens * q3.w;
            }
        }
        __syncthreads();
    }

    // reset bin counter for the next launch (keeps the no-memset invariant)
    if (t == 0) g_cnt[b] = 0;

    const int idx = (ix * DIMY + iy) * DIMZ + iz;
    gdens[idx] = accd;

    const float s = 1.0f / fmaxf(accd, 1e-6f);
    f3w += 1e-5f;  // reference seeds channel 15 with 1e-5 before normalize
    float4* fp = (float4*)(gfeat + (size_t)idx * NDIMS);
    fp[0] = make_float4(f0x * s, f0y * s, f0z * s, f0w * s);
    fp[1] = make_float4(f1x * s, f1y * s, f1z * s, f1w * s);
    fp[2] = make_float4(f2x * s, f2y * s, f2z * s, f2w * s);
    fp[3] = make_float4(f3x * s, f3y * s, f3z * s, f3w * s);
}

extern "C" void kernel_launch(void* const* d_in, const int* in_sizes, int n_in,
                              void* d_out, int out_size) {
    const float* means = (const float*)d_in[0];   // [N,3]
    const float* covs  = (const float*)d_in[1];   // [N,3,3]
    const float* opac  = (const float*)d_in[2];   // [N]
    const float* feats = (const float*)d_in[3];   // [N,16]
    const int n_gauss = in_sizes[2];

    float* gdens = (float*)d_out;                                  // [200*200*16]
    float* gfeat = gdens + (size_t)DIMX * DIMY * DIMZ;             // [...,16]

    k_bin<<<(n_gauss + 255) / 256, 256>>>(means, covs, opac, n_gauss);
    k_gather<<<NTILES, 256>>>((const float4*)feats, gdens, gfeat);
}